// round 1
// baseline (speedup 1.0000x reference)
#include <cuda_runtime.h>

#define MD   96
#define MN   9216
#define NS   32
#define TB   48

// scratch (device globals; no allocation allowed)
__device__ float g_LM[MN];
__device__ float g_LN[MN];
__device__ float g_Gy[NS * MN];   // [s][p][nu]
__device__ float g_Gx[NS * MN];   // [s][mi][q]
__device__ float g_H [NS * MN];   // [s][mm][nu]
__device__ float g_P [NS * MN];   // [t][nn][mm]
__device__ float g_O1[NS * MN];   // [t][ni][mi]
__device__ float g_O2[NS * MN];   // [t][ni][mi]

__device__ __forceinline__ float wrapf(float v) {
    float r = fmodf(v + 1.0f, 2.0f);
    if (r < 0.0f) r += 2.0f;
    return r - 1.0f;
}

// ---------------------------------------------------------------------------
// K0: LM = DM^T DM, LN = DN^T DN.  grid 8 = {mat(2)} x {tile(4)}
// ---------------------------------------------------------------------------
__global__ __launch_bounds__(256) void k0_gram(const float* __restrict__ DM,
                                               const float* __restrict__ DN) {
    __shared__ float As[TB][97];
    __shared__ float Bs[MD][TB + 1];
    int bx = blockIdx.x;
    int mat = bx >> 2, tile = bx & 3;
    int rb = (tile >> 1) * TB, cb = (tile & 1) * TB;
    const float* D = mat ? DN : DM;
    float* O = mat ? g_LN : g_LM;
    int tid = threadIdx.y * 16 + threadIdx.x;
    for (int idx = tid; idx < TB * MD; idx += 256) {
        int i = idx / MD, p = idx % MD;
        As[i][p] = D[p * MD + rb + i];               // A[i][p] = D[p][rb+i]
    }
    for (int idx = tid; idx < MD * TB; idx += 256) {
        int p = idx / TB, j = idx % TB;
        Bs[p][j] = D[p * MD + cb + j];
    }
    __syncthreads();
    int r0 = threadIdx.y * 3, c0 = threadIdx.x * 3;
    float acc[3][3] = {};
#pragma unroll 8
    for (int k = 0; k < MD; k++) {
        float a0 = As[r0][k], a1 = As[r0 + 1][k], a2 = As[r0 + 2][k];
        float b0 = Bs[k][c0], b1 = Bs[k][c0 + 1], b2 = Bs[k][c0 + 2];
        acc[0][0] += a0 * b0; acc[0][1] += a0 * b1; acc[0][2] += a0 * b2;
        acc[1][0] += a1 * b0; acc[1][1] += a1 * b1; acc[1][2] += a1 * b2;
        acc[2][0] += a2 * b0; acc[2][1] += a2 * b1; acc[2][2] += a2 * b2;
    }
#pragma unroll
    for (int i = 0; i < 3; i++)
#pragma unroll
        for (int j = 0; j < 3; j++)
            O[(rb + r0 + i) * MD + cb + c0 + j] = acc[i][j];
}

// ---------------------------------------------------------------------------
// K1: Gy[s] = wrap(DM @ Xs), Gx[s] = wrap(Xs @ DN^T).
// grid (32 s, 8 = which*4+tile)
// ---------------------------------------------------------------------------
__global__ __launch_bounds__(256) void k1_diffs(const float* __restrict__ x,
                                                const float* __restrict__ DM,
                                                const float* __restrict__ DN) {
    __shared__ float As[TB][97];
    __shared__ float Bs[MD][TB + 1];
    int s = blockIdx.x;
    int which = blockIdx.y >> 2;
    int tile = blockIdx.y & 3;
    int rb = (tile >> 1) * TB, cb = (tile & 1) * TB;
    const float* Xs = x + s * MN;
    int tid = threadIdx.y * 16 + threadIdx.x;
    if (which == 0) {
        // C[p][nu] = sum_mi DM[p][mi] * Xs[mi][nu]
        for (int idx = tid; idx < TB * MD; idx += 256) {
            int i = idx / MD, k = idx % MD;
            As[i][k] = DM[(rb + i) * MD + k];
        }
        for (int idx = tid; idx < MD * TB; idx += 256) {
            int k = idx / TB, j = idx % TB;
            Bs[k][j] = Xs[k * MD + cb + j];
        }
    } else {
        // C[mi][q] = sum_ni Xs[mi][ni] * DN[q][ni]
        for (int idx = tid; idx < TB * MD; idx += 256) {
            int i = idx / MD, k = idx % MD;
            As[i][k] = Xs[(rb + i) * MD + k];
        }
        for (int idx = tid; idx < MD * TB; idx += 256) {
            int k = idx / TB, j = idx % TB;
            Bs[k][j] = DN[(cb + j) * MD + k];
        }
    }
    __syncthreads();
    int r0 = threadIdx.y * 3, c0 = threadIdx.x * 3;
    float acc[3][3] = {};
#pragma unroll 8
    for (int k = 0; k < MD; k++) {
        float a0 = As[r0][k], a1 = As[r0 + 1][k], a2 = As[r0 + 2][k];
        float b0 = Bs[k][c0], b1 = Bs[k][c0 + 1], b2 = Bs[k][c0 + 2];
        acc[0][0] += a0 * b0; acc[0][1] += a0 * b1; acc[0][2] += a0 * b2;
        acc[1][0] += a1 * b0; acc[1][1] += a1 * b1; acc[1][2] += a1 * b2;
        acc[2][0] += a2 * b0; acc[2][1] += a2 * b1; acc[2][2] += a2 * b2;
    }
    float* O = which ? g_Gx : g_Gy;
#pragma unroll
    for (int i = 0; i < 3; i++)
#pragma unroll
        for (int j = 0; j < 3; j++)
            O[s * MN + (rb + r0 + i) * MD + cb + c0 + j] = wrapf(acc[i][j]);
}

// ---------------------------------------------------------------------------
// K2a: H[s][mm][nu] = sum_p DM[p][mm] * Gy[s][p][nu].  grid (32, 4)
// ---------------------------------------------------------------------------
__global__ __launch_bounds__(256) void k2a_H(const float* __restrict__ DM) {
    __shared__ float As[TB][97];
    __shared__ float Bs[MD][TB + 1];
    int s = blockIdx.x;
    int tile = blockIdx.y;
    int rb = (tile >> 1) * TB, cb = (tile & 1) * TB;
    int tid = threadIdx.y * 16 + threadIdx.x;
    for (int idx = tid; idx < TB * MD; idx += 256) {
        int i = idx / MD, k = idx % MD;
        As[i][k] = DM[k * MD + rb + i];              // DM^T
    }
    for (int idx = tid; idx < MD * TB; idx += 256) {
        int k = idx / TB, j = idx % TB;
        Bs[k][j] = g_Gy[s * MN + k * MD + cb + j];
    }
    __syncthreads();
    int r0 = threadIdx.y * 3, c0 = threadIdx.x * 3;
    float acc[3][3] = {};
#pragma unroll 8
    for (int k = 0; k < MD; k++) {
        float a0 = As[r0][k], a1 = As[r0 + 1][k], a2 = As[r0 + 2][k];
        float b0 = Bs[k][c0], b1 = Bs[k][c0 + 1], b2 = Bs[k][c0 + 2];
        acc[0][0] += a0 * b0; acc[0][1] += a0 * b1; acc[0][2] += a0 * b2;
        acc[1][0] += a1 * b0; acc[1][1] += a1 * b1; acc[1][2] += a1 * b2;
        acc[2][0] += a2 * b0; acc[2][1] += a2 * b1; acc[2][2] += a2 * b2;
    }
#pragma unroll
    for (int i = 0; i < 3; i++)
#pragma unroll
        for (int j = 0; j < 3; j++)
            g_H[s * MN + (rb + r0 + i) * MD + cb + c0 + j] = acc[i][j];
}

// ---------------------------------------------------------------------------
// K2b: P[t][nn][mm] = sum_q DN[q][nn]*Gx[q%32][mm][3t+q/32]
//                   + H[nn%32][mm][3t+nn/32] + eta*x[s2][mm][nn]
// grid (32 t, 4)
// ---------------------------------------------------------------------------
__global__ __launch_bounds__(256) void k2b_P(const float* __restrict__ x,
                                             const float* __restrict__ DN,
                                             const float* __restrict__ eta) {
    __shared__ float As[TB][97];
    __shared__ float Bs[MD][TB + 1];
    int t = blockIdx.x;
    int tile = blockIdx.y;
    int rb = (tile >> 1) * TB, cb = (tile & 1) * TB;
    int tid = threadIdx.y * 16 + threadIdx.x;
    for (int idx = tid; idx < TB * MD; idx += 256) {
        int i = idx / MD, k = idx % MD;
        As[i][k] = DN[k * MD + rb + i];              // DN^T
    }
    for (int idx = tid; idx < MD * TB; idx += 256) {
        int k = idx / TB, j = idx % TB;              // k = q
        Bs[k][j] = g_Gx[(k & 31) * MN + (cb + j) * MD + 3 * t + (k >> 5)];
    }
    __syncthreads();
    int r0 = threadIdx.y * 3, c0 = threadIdx.x * 3;
    float acc[3][3] = {};
#pragma unroll 8
    for (int k = 0; k < MD; k++) {
        float a0 = As[r0][k], a1 = As[r0 + 1][k], a2 = As[r0 + 2][k];
        float b0 = Bs[k][c0], b1 = Bs[k][c0 + 1], b2 = Bs[k][c0 + 2];
        acc[0][0] += a0 * b0; acc[0][1] += a0 * b1; acc[0][2] += a0 * b2;
        acc[1][0] += a1 * b0; acc[1][1] += a1 * b1; acc[1][2] += a1 * b2;
        acc[2][0] += a2 * b0; acc[2][1] += a2 * b1; acc[2][2] += a2 * b2;
    }
    float ev = eta[0];
    int s2 = 4 * (t & 7) + (t >> 3);
#pragma unroll
    for (int i = 0; i < 3; i++)
#pragma unroll
        for (int j = 0; j < 3; j++) {
            int r = rb + r0 + i;                     // nn
            int c = cb + c0 + j;                     // mm
            float hterm = g_H[(r & 31) * MN + c * MD + 3 * t + (r >> 5)];
            float xterm = ev * x[s2 * MN + c * MD + r];
            g_P[t * MN + r * MD + c] = acc[i][j] + hterm + xterm;
        }
}

// ---------------------------------------------------------------------------
// K3: part==0: O1 = P_t @ LM + eta*P_t ;  part==1: O2 = LN @ P_t.
// grid (32 t, 8 = part*4+tile)
// ---------------------------------------------------------------------------
__global__ __launch_bounds__(256) void k3_parts(const float* __restrict__ eta) {
    __shared__ float As[TB][97];
    __shared__ float Bs[MD][TB + 1];
    int t = blockIdx.x;
    int part = blockIdx.y >> 2;
    int tile = blockIdx.y & 3;
    int rb = (tile >> 1) * TB, cb = (tile & 1) * TB;
    int tid = threadIdx.y * 16 + threadIdx.x;
    if (part == 0) {
        for (int idx = tid; idx < TB * MD; idx += 256) {
            int i = idx / MD, k = idx % MD;
            As[i][k] = g_P[t * MN + (rb + i) * MD + k];
        }
        for (int idx = tid; idx < MD * TB; idx += 256) {
            int k = idx / TB, j = idx % TB;
            Bs[k][j] = g_LM[k * MD + cb + j];
        }
    } else {
        for (int idx = tid; idx < TB * MD; idx += 256) {
            int i = idx / MD, k = idx % MD;
            As[i][k] = g_LN[(rb + i) * MD + k];
        }
        for (int idx = tid; idx < MD * TB; idx += 256) {
            int k = idx / TB, j = idx % TB;
            Bs[k][j] = g_P[t * MN + k * MD + cb + j];
        }
    }
    __syncthreads();
    int r0 = threadIdx.y * 3, c0 = threadIdx.x * 3;
    float acc[3][3] = {};
#pragma unroll 8
    for (int k = 0; k < MD; k++) {
        float a0 = As[r0][k], a1 = As[r0 + 1][k], a2 = As[r0 + 2][k];
        float b0 = Bs[k][c0], b1 = Bs[k][c0 + 1], b2 = Bs[k][c0 + 2];
        acc[0][0] += a0 * b0; acc[0][1] += a0 * b1; acc[0][2] += a0 * b2;
        acc[1][0] += a1 * b0; acc[1][1] += a1 * b1; acc[1][2] += a1 * b2;
        acc[2][0] += a2 * b0; acc[2][1] += a2 * b1; acc[2][2] += a2 * b2;
    }
    if (part == 0) {
        float ev = eta[0];
#pragma unroll
        for (int i = 0; i < 3; i++)
#pragma unroll
            for (int j = 0; j < 3; j++) {
                int r = rb + r0 + i, c = cb + c0 + j;
                g_O1[t * MN + r * MD + c] = acc[i][j] + ev * g_P[t * MN + r * MD + c];
            }
    } else {
#pragma unroll
        for (int i = 0; i < 3; i++)
#pragma unroll
            for (int j = 0; j < 3; j++) {
                int r = rb + r0 + i, c = cb + c0 + j;
                g_O2[t * MN + r * MD + c] = acc[i][j];
            }
    }
}

// ---------------------------------------------------------------------------
// K3c: out[bi,ci,mi,ni] = O1[t][ni][mi] + O2[t][ni][mi],  s2 = 4(t&7)+(t>>3)
// ---------------------------------------------------------------------------
__global__ __launch_bounds__(256) void k3c_out(float* __restrict__ out) {
    int t = blockIdx.x;
    int s2 = 4 * (t & 7) + (t >> 3);
    for (int idx = threadIdx.x; idx < MN; idx += 256) {
        int mi = idx / MD, ni = idx % MD;
        out[s2 * MN + mi * MD + ni] =
            g_O1[t * MN + ni * MD + mi] + g_O2[t * MN + ni * MD + mi];
    }
}

// ---------------------------------------------------------------------------
extern "C" void kernel_launch(void* const* d_in, const int* in_sizes, int n_in,
                              void* d_out, int out_size) {
    // identify inputs by size (order: x, eta, A_w, DM, DN)
    int ix = 0, ie = 1, idm = 3, idn = 4;
    {
        int found_d = 0;
        for (int i = 0; i < n_in; i++) {
            if (in_sizes[i] == 294912) ix = i;
            else if (in_sizes[i] == 1) ie = i;
            else if (in_sizes[i] == 9216) {
                if (found_d == 0) { idm = i; found_d = 1; }
                else idn = i;
            }
        }
    }
    const float* x   = (const float*)d_in[ix];
    const float* eta = (const float*)d_in[ie];
    const float* DM  = (const float*)d_in[idm];
    const float* DN  = (const float*)d_in[idn];
    float* out = (float*)d_out;

    dim3 thr(16, 16);
    k0_gram <<<8,            thr>>>(DM, DN);
    k1_diffs<<<dim3(32, 8),  thr>>>(x, DM, DN);
    k2a_H   <<<dim3(32, 4),  thr>>>(DM);
    k2b_P   <<<dim3(32, 4),  thr>>>(x, DN, eta);
    k3_parts<<<dim3(32, 8),  thr>>>(eta);
    k3c_out <<<32, 256>>>(out);
}

// round 4
// speedup vs baseline: 1.8945x; 1.8945x over previous
#include <cuda_runtime.h>

#define MD   96
#define MN   9216
#define NS   32
#define PA   100   // As pitch (floats): 400B rows, 16B-aligned
#define PB   52    // Bs pitch (floats): 208B rows, 16B-aligned

// scratch (device globals; allocation is forbidden)
__device__ float g_LM [MN];
__device__ float g_LN [MN];
__device__ float g_Gy [NS * MN];   // [s][p][nu]
__device__ float g_GxP[NS * MN];   // [t][q][mm]  (pre-permuted for K2b)
__device__ float g_HP [NS * MN];   // [t][nn][mm] (pre-permuted for K2b)
__device__ float g_P  [NS * MN];   // [t][nn][mm]

__device__ __forceinline__ float wrapf(float v) {
    float r = fmodf(v + 1.0f, 2.0f);
    if (r < 0.0f) r += 2.0f;
    return r - 1.0f;
}

// As[i][k] = src[(rb+i)*96 + k]   (row-contiguous, float4)
__device__ __forceinline__ void loadA_vec(float (*As)[PA], const float* __restrict__ src,
                                          int rb, int tid) {
    for (int idx = tid; idx < 48 * 24; idx += 256) {
        int i = idx / 24, k4 = idx % 24;
        float4 v = *(const float4*)(src + (rb + i) * MD + 4 * k4);
        *(float4*)(&As[i][4 * k4]) = v;
    }
}

// As[i][k] = src[k*96 + rb + i]   (transpose; coalesced global read)
__device__ __forceinline__ void loadA_trans(float (*As)[PA], const float* __restrict__ src,
                                            int rb, int tid) {
    for (int idx = tid; idx < 48 * MD; idx += 256) {
        int i = idx % 48, k = idx / 48;
        As[i][k] = src[k * MD + rb + i];
    }
}

// Bs[k][j] = src[k*96 + cb + j]   (row-contiguous, float4)
__device__ __forceinline__ void loadB_vec(float (*Bs)[PB], const float* __restrict__ src,
                                          int cb, int tid) {
    for (int idx = tid; idx < MD * 12; idx += 256) {
        int k = idx / 12, j4 = idx % 12;
        float4 v = *(const float4*)(src + k * MD + cb + 4 * j4);
        *(float4*)(&Bs[k][4 * j4]) = v;
    }
}

// Bs[k][j] = src[(cb+j)*96 + k]   (transpose; coalesced global read)
__device__ __forceinline__ void loadB_trans(float (*Bs)[PB], const float* __restrict__ src,
                                            int cb, int tid) {
    for (int idx = tid; idx < MD * 48; idx += 256) {
        int k = idx % MD, j = idx / MD;
        Bs[k][j] = src[(cb + j) * MD + k];
    }
}

__device__ __forceinline__ void mm_accum(const float (*As)[PA], const float (*Bs)[PB],
                                         float acc[3][3], int r0, int c0) {
#pragma unroll 8
    for (int k = 0; k < MD; k++) {
        float a0 = As[r0][k], a1 = As[r0 + 1][k], a2 = As[r0 + 2][k];
        float b0 = Bs[k][c0], b1 = Bs[k][c0 + 1], b2 = Bs[k][c0 + 2];
        acc[0][0] += a0 * b0; acc[0][1] += a0 * b1; acc[0][2] += a0 * b2;
        acc[1][0] += a1 * b0; acc[1][1] += a1 * b1; acc[1][2] += a1 * b2;
        acc[2][0] += a2 * b0; acc[2][1] += a2 * b1; acc[2][2] += a2 * b2;
    }
}

// ---------------------------------------------------------------------------
// S1: grid 264.  b<8: gram (LM,LN).  b>=8: diffs Gy / GxP.
// ---------------------------------------------------------------------------
__global__ __launch_bounds__(256) void s1_gram_diffs(const float* __restrict__ x,
                                                     const float* __restrict__ DM,
                                                     const float* __restrict__ DN) {
    __shared__ float As[48][PA];
    __shared__ float Bs[MD][PB];
    int tid = threadIdx.y * 16 + threadIdx.x;
    int r0 = threadIdx.y * 3, c0 = threadIdx.x * 3;
    float acc[3][3] = {};
    int b = blockIdx.x;
    if (b < 8) {
        int mat = b >> 2, tile = b & 3;
        int rb = (tile >> 1) * 48, cb = (tile & 1) * 48;
        const float* D = mat ? DN : DM;
        float* O = mat ? g_LN : g_LM;
        loadA_trans(As, D, rb, tid);   // As[i][p] = D[p][rb+i]  (D^T)
        loadB_vec(Bs, D, cb, tid);
        __syncthreads();
        mm_accum(As, Bs, acc, r0, c0);
#pragma unroll
        for (int i = 0; i < 3; i++)
#pragma unroll
            for (int j = 0; j < 3; j++)
                O[(rb + r0 + i) * MD + cb + c0 + j] = acc[i][j];
    } else {
        int idx2 = b - 8;
        int s = idx2 >> 3, sub = idx2 & 7;
        int which = sub >> 2, tile = sub & 3;
        int rb = (tile >> 1) * 48, cb = (tile & 1) * 48;
        const float* Xs = x + s * MN;
        if (which == 0) {       // Gy[p][nu] = sum_mi DM[p][mi] Xs[mi][nu]
            loadA_vec(As, DM, rb, tid);
            loadB_vec(Bs, Xs, cb, tid);
        } else {                // Gx[mi][q] = sum_ni Xs[mi][ni] DN[q][ni]
            loadA_vec(As, Xs, rb, tid);
            loadB_trans(Bs, DN, cb, tid);
        }
        __syncthreads();
        mm_accum(As, Bs, acc, r0, c0);
        if (which == 0) {
#pragma unroll
            for (int i = 0; i < 3; i++)
#pragma unroll
                for (int j = 0; j < 3; j++)
                    g_Gy[s * MN + (rb + r0 + i) * MD + cb + c0 + j] = wrapf(acc[i][j]);
        } else {
            // scatter into GxP[t][q][mm]:  t=nu/3, q=s+32*(nu%3), mm=mi
#pragma unroll
            for (int i = 0; i < 3; i++)
#pragma unroll
                for (int j = 0; j < 3; j++) {
                    int mi = rb + r0 + i, nu = cb + c0 + j;
                    int t = nu / 3, e = nu - 3 * t;
                    g_GxP[t * MN + (s + 32 * e) * MD + mi] = wrapf(acc[i][j]);
                }
        }
    }
}

// ---------------------------------------------------------------------------
// S2: grid 128.  H[s][mm][nu] = sum_p DM[p][mm] Gy[s][p][nu], scattered to HP.
// ---------------------------------------------------------------------------
__global__ __launch_bounds__(256) void s2_H(const float* __restrict__ DM) {
    __shared__ float As[48][PA];
    __shared__ float Bs[MD][PB];
    int tid = threadIdx.y * 16 + threadIdx.x;
    int r0 = threadIdx.y * 3, c0 = threadIdx.x * 3;
    int s = blockIdx.x >> 2, tile = blockIdx.x & 3;
    int rb = (tile >> 1) * 48, cb = (tile & 1) * 48;
    loadA_trans(As, DM, rb, tid);               // DM^T
    loadB_vec(Bs, g_Gy + s * MN, cb, tid);
    __syncthreads();
    float acc[3][3] = {};
    mm_accum(As, Bs, acc, r0, c0);
    // scatter into HP[t][nn][mm]: t=nu/3, nn=s+32*(nu%3), mm
#pragma unroll
    for (int i = 0; i < 3; i++)
#pragma unroll
        for (int j = 0; j < 3; j++) {
            int mm = rb + r0 + i, nu = cb + c0 + j;
            int t = nu / 3, e = nu - 3 * t;
            g_HP[t * MN + (s + 32 * e) * MD + mm] = acc[i][j];
        }
}

// ---------------------------------------------------------------------------
// S3: grid 128.  P[t][nn][mm] = sum_q DN^T[nn][q] GxP[t][q][mm]
//                             + HP[t][nn][mm] + eta * x[s2][mm][nn]
// ---------------------------------------------------------------------------
__global__ __launch_bounds__(256) void s3_P(const float* __restrict__ x,
                                            const float* __restrict__ DN,
                                            const float* __restrict__ eta) {
    __shared__ float As[48][PA];
    __shared__ float Bs[MD][PB];
    __shared__ float xs[48][48];   // xs[i][j] = x[s2][cb+i][rb+j]
    int tid = threadIdx.y * 16 + threadIdx.x;
    int r0 = threadIdx.y * 3, c0 = threadIdx.x * 3;
    int t = blockIdx.x >> 2, tile = blockIdx.x & 3;
    int rb = (tile >> 1) * 48, cb = (tile & 1) * 48;
    int s2 = 4 * (t & 7) + (t >> 3);
    loadA_trans(As, DN, rb, tid);               // DN^T
    loadB_vec(Bs, g_GxP + t * MN, cb, tid);
    for (int idx = tid; idx < 48 * 12; idx += 256) {
        int i = idx / 12, j4 = idx % 12;
        float4 v = *(const float4*)(x + s2 * MN + (cb + i) * MD + rb + 4 * j4);
        *(float4*)(&xs[i][4 * j4]) = v;
    }
    __syncthreads();
    float acc[3][3] = {};
    mm_accum(As, Bs, acc, r0, c0);
    float ev = eta[0];
#pragma unroll
    for (int i = 0; i < 3; i++)
#pragma unroll
        for (int j = 0; j < 3; j++) {
            int r = rb + r0 + i;    // nn
            int c = cb + c0 + j;    // mm
            g_P[t * MN + r * MD + c] = acc[i][j]
                + g_HP[t * MN + r * MD + c]
                + ev * xs[c - cb][r - rb];
        }
}

// ---------------------------------------------------------------------------
// S4: grid 128.  O = P@LM + LN@P + eta*P;  out[s2][c][r] = O[r][c].
// ---------------------------------------------------------------------------
__global__ __launch_bounds__(256) void s4_out(const float* __restrict__ eta,
                                              float* __restrict__ out) {
    __shared__ float As[48][PA];
    __shared__ float Bs[MD][PB];
    int tid = threadIdx.y * 16 + threadIdx.x;
    int r0 = threadIdx.y * 3, c0 = threadIdx.x * 3;
    int t = blockIdx.x >> 2, tile = blockIdx.x & 3;
    int rb = (tile >> 1) * 48, cb = (tile & 1) * 48;
    int s2 = 4 * (t & 7) + (t >> 3);
    const float* Pt = g_P + t * MN;
    float acc[3][3] = {};

    // phase 1: P_t @ LM
    loadA_vec(As, Pt, rb, tid);
    loadB_vec(Bs, g_LM, cb, tid);
    __syncthreads();
    mm_accum(As, Bs, acc, r0, c0);
    __syncthreads();

    // phase 2: LN @ P_t
    loadA_vec(As, g_LN, rb, tid);
    loadB_vec(Bs, Pt, cb, tid);
    __syncthreads();
    mm_accum(As, Bs, acc, r0, c0);

    // + eta * P_t
    float ev = eta[0];
#pragma unroll
    for (int i = 0; i < 3; i++)
#pragma unroll
        for (int j = 0; j < 3; j++)
            acc[i][j] += ev * Pt[(rb + r0 + i) * MD + cb + c0 + j];

    // transpose through smem, then coalesced store: out[s2][cb+cl][rb+rl]
    __syncthreads();
    float* Ts = &As[0][0];       // 48x48 tile, pitch 49
#pragma unroll
    for (int i = 0; i < 3; i++)
#pragma unroll
        for (int j = 0; j < 3; j++)
            Ts[(c0 + j) * 49 + (r0 + i)] = acc[i][j];
    __syncthreads();
    for (int idx = tid; idx < 48 * 48; idx += 256) {
        int cl = idx / 48, rl = idx % 48;
        out[s2 * MN + (cb + cl) * MD + rb + rl] = Ts[cl * 49 + rl];
    }
}

// ---------------------------------------------------------------------------
extern "C" void kernel_launch(void* const* d_in, const int* in_sizes, int n_in,
                              void* d_out, int out_size) {
    // inputs: x(294912), eta(1), A_w(84934656, unused), DM(9216), DN(9216)
    int ix = 0, ie = 1, idm = 3, idn = 4;
    {
        int found_d = 0;
        for (int i = 0; i < n_in; i++) {
            if (in_sizes[i] == 294912) ix = i;
            else if (in_sizes[i] == 1) ie = i;
            else if (in_sizes[i] == 9216) {
                if (found_d == 0) { idm = i; found_d = 1; }
                else idn = i;
            }
        }
    }
    const float* x   = (const float*)d_in[ix];
    const float* eta = (const float*)d_in[ie];
    const float* DM  = (const float*)d_in[idm];
    const float* DN  = (const float*)d_in[idn];
    float* out = (float*)d_out;

    dim3 thr(16, 16);
    s1_gram_diffs<<<264, thr>>>(x, DM, DN);
    s2_H         <<<128, thr>>>(DM);
    s3_P         <<<128, thr>>>(x, DN, eta);
    s4_out       <<<128, thr>>>(eta, out);
}